// round 12
// baseline (speedup 1.0000x reference)
#include <cuda_runtime.h>

#define NN 50000
#define NE 800000
#define HD 64
#define NL 4
#define AS_LD 68

// ---------------- device scratch ----------------
__device__ __align__(16) float g_h[2][(size_t)NN * HD];
__device__ __align__(16) float g_S[(size_t)NN * HD];        // segment-summed relu(pre1) per node
__device__ __align__(16) float g_uv[(size_t)NN * 128];      // u (cols 0-63), v (cols 64-127)
// CSR (sorted by dst)
__device__ __align__(16) int   g_cnt[NN];
__device__ __align__(16) int   g_fill[NN];
__device__ __align__(16) int   g_rowptr[NN + 1];
__device__ __align__(16) int   g_src_s[NE];
__device__ __align__(16) float4 g_evec_s[NE];
// folded weights
__device__ __align__(16) float g_wfold[NL][3 * 64];         // edge_enc_w @ W1_e
__device__ __align__(16) float g_b1eff[NL][64];             // b1 + eeb @ W1_e
__device__ __align__(16) float g_wuv[NL][64 * 128];         // [W1a | W1b]
__device__ __align__(16) float g_nwf[NL][128 * 64];         // [M1_top ; W2 @ M1_bot]
__device__ __align__(16) float g_q[NL][64];                 // b2 @ M1_bot

// ---------------- f32x2 packed-FMA helpers ----------------
__device__ __forceinline__ void ffma2(unsigned long long& d, unsigned long long a, unsigned long long b) {
    asm("fma.rn.f32x2 %0, %1, %2, %0;" : "+l"(d) : "l"(a), "l"(b));
}
__device__ __forceinline__ unsigned long long splat2(float x) {
    unsigned long long r; asm("mov.b64 %0, {%1, %1};" : "=l"(r) : "f"(x)); return r;
}
__device__ __forceinline__ float2 unpk(unsigned long long v) {
    float2 f; asm("mov.b64 {%0, %1}, %2;" : "=f"(f.x), "=f"(f.y) : "l"(v)); return f;
}

#define GEMM_STEP(ACC, APTR, BPTR) do {                                        \
    float4 a4_ = *reinterpret_cast<const float4*>(APTR);                        \
    ulonglong2 bb_ = *reinterpret_cast<const ulonglong2*>(BPTR);                \
    unsigned long long s_;                                                      \
    s_ = splat2(a4_.x); ffma2(ACC[0][0], s_, bb_.x); ffma2(ACC[0][1], s_, bb_.y); \
    s_ = splat2(a4_.y); ffma2(ACC[1][0], s_, bb_.x); ffma2(ACC[1][1], s_, bb_.y); \
    s_ = splat2(a4_.z); ffma2(ACC[2][0], s_, bb_.x); ffma2(ACC[2][1], s_, bb_.y); \
    s_ = splat2(a4_.w); ffma2(ACC[3][0], s_, bb_.x); ffma2(ACC[3][1], s_, bb_.y); \
} while (0)

#define GEMM_STEP2(ACU, ACV, APTR, BU, BV) do {                                \
    float4 a4_ = *reinterpret_cast<const float4*>(APTR);                        \
    ulonglong2 bu_ = *reinterpret_cast<const ulonglong2*>(BU);                  \
    ulonglong2 bv_ = *reinterpret_cast<const ulonglong2*>(BV);                  \
    unsigned long long s_;                                                      \
    s_ = splat2(a4_.x); ffma2(ACU[0][0], s_, bu_.x); ffma2(ACU[0][1], s_, bu_.y); ffma2(ACV[0][0], s_, bv_.x); ffma2(ACV[0][1], s_, bv_.y); \
    s_ = splat2(a4_.y); ffma2(ACU[1][0], s_, bu_.x); ffma2(ACU[1][1], s_, bu_.y); ffma2(ACV[1][0], s_, bv_.x); ffma2(ACV[1][1], s_, bv_.y); \
    s_ = splat2(a4_.z); ffma2(ACU[2][0], s_, bu_.x); ffma2(ACU[2][1], s_, bu_.y); ffma2(ACV[2][0], s_, bv_.x); ffma2(ACV[2][1], s_, bv_.y); \
    s_ = splat2(a4_.w); ffma2(ACU[3][0], s_, bu_.x); ffma2(ACU[3][1], s_, bu_.y); ffma2(ACV[3][0], s_, bv_.x); ffma2(ACV[3][1], s_, bv_.y); \
} while (0)

// ---------------- CSR build (no intermediates) ----------------
__global__ void zero_counters() {
    int i = blockIdx.x * 256 + threadIdx.x;
    if (i < NN) { g_cnt[i] = 0; g_fill[i] = 0; }
}

__global__ void prep_cnt(const int* __restrict__ ei) {
    int i = blockIdx.x * 256 + threadIdx.x;
    if (i >= NE) return;
    int d = min(max(ei[NE + i], 0), NN - 1);
    atomicAdd(&g_cnt[d], 1);
}

#define SCN_C 49   // ceil(50000/1024)
__global__ void scan_counts() {
    __shared__ int part[1024];
    int t = threadIdx.x;
    int base = t * SCN_C;
    int sum = 0;
    for (int i = 0; i < SCN_C; i++) {
        int idx = base + i;
        if (idx < NN) sum += g_cnt[idx];
    }
    part[t] = sum;
    __syncthreads();
    for (int off = 1; off < 1024; off <<= 1) {
        int v = (t >= off) ? part[t - off] : 0;
        __syncthreads();
        if (t >= off) part[t] += v;
        __syncthreads();
    }
    int run = (t > 0) ? part[t - 1] : 0;
    for (int i = 0; i < SCN_C; i++) {
        int idx = base + i;
        if (idx < NN) { g_rowptr[idx] = run; run += g_cnt[idx]; }
    }
    if (t == 1023) g_rowptr[NN] = run;
}

__global__ void fill_csr(const int* __restrict__ ei, const float* __restrict__ pos) {
    int i = blockIdx.x * 256 + threadIdx.x;
    if (i >= NE) return;
    int s = min(max(ei[i], 0), NN - 1);
    int d = min(max(ei[NE + i], 0), NN - 1);
    int p = g_rowptr[d] + atomicAdd(&g_fill[d], 1);
    const float* ps = pos + 3 * (size_t)s;
    const float* pd = pos + 3 * (size_t)d;
    g_src_s[p] = s;
    g_evec_s[p] = make_float4(pd[0] - ps[0], pd[1] - ps[1], pd[2] - ps[2], 0.f);
}

// ---------------- one combined weight-prep kernel ----------------
// ranges: [0,768) wfold | [768,1024) b1eff | [1024,1280) q | [1280,34048) wuv | [34048,66816) nwf
#define PREPW_TOT (768 + 256 + 256 + NL * 8192 + NL * 8192)
__global__ void prep_weights(const float* __restrict__ ew1, const float* __restrict__ eew,
                             const float* __restrict__ eeb, const float* __restrict__ eb1,
                             const float* __restrict__ eb2, const float* __restrict__ nw1,
                             const float* __restrict__ ew2) {
    int idx = blockIdx.x * 256 + threadIdx.x;
    if (idx >= PREPW_TOT) return;
    if (idx < 768) {
        int j = idx & 63;
        int c = (idx >> 6) % 3;
        int l = idx / 192;
        const float* w = ew1 + (size_t)l * 192 * 64 + 128 * 64 + j;
        float v = 0.f;
        #pragma unroll 8
        for (int m = 0; m < 64; m++) v += eew[c * 64 + m] * w[(size_t)m * 64];
        g_wfold[l][c * 64 + j] = v;
    } else if (idx < 1024) {
        int r = idx - 768;
        int j = r & 63;
        int l = r >> 6;
        float v = eb1[l * 64 + j];
        const float* w = ew1 + (size_t)l * 192 * 64 + 128 * 64 + j;
        #pragma unroll 8
        for (int m = 0; m < 64; m++) v += eeb[m] * w[(size_t)m * 64];
        g_b1eff[l][j] = v;
    } else if (idx < 1280) {
        int r = idx - 1024;
        int j = r & 63;
        int l = r >> 6;
        const float* m1 = nw1 + (size_t)l * 128 * 64;
        float v = 0.f;
        #pragma unroll 8
        for (int m = 0; m < 64; m++) v += eb2[l * 64 + m] * m1[(64 + m) * 64 + j];
        g_q[l][j] = v;
    } else if (idx < 34048) {
        int r = idx - 1280;
        int j = r & 127;
        int k = (r >> 7) & 63;
        int l = r >> 13;
        const float* base = ew1 + (size_t)l * 192 * 64;
        g_wuv[l][k * 128 + j] = (j < 64) ? base[k * 64 + j] : base[(64 + k) * 64 + (j - 64)];
    } else {
        int r = idx - 34048;
        int j = r & 63;
        int k = (r >> 6) & 127;
        int l = r >> 13;
        const float* m1 = nw1 + (size_t)l * 128 * 64;
        float v;
        if (k < 64) {
            v = m1[k * 64 + j];
        } else {
            int p = k - 64;
            const float* w2 = ew2 + (size_t)l * 64 * 64 + p * 64;
            v = 0.f;
            #pragma unroll 8
            for (int m = 0; m < 64; m++) v += w2[m] * m1[(64 + m) * 64 + j];
        }
        g_nwf[l][k * 64 + j] = v;
    }
}

__global__ void encoder(const float* __restrict__ nf, const float* __restrict__ w,
                        const float* __restrict__ b) {
    int idx = blockIdx.x * 256 + threadIdx.x;
    if (idx >= NN * HD) return;
    int j = idx & 63;
    int n = idx >> 6;
    float acc = b[j];
    acc += nf[n * 3 + 0] * w[j] + nf[n * 3 + 1] * w[64 + j] + nf[n * 3 + 2] * w[128 + j];
    g_h[0][idx] = acc;
}

// ---------------- uv kernel: uv[n] = h[n] @ [W1a|W1b] ----------------
static constexpr int UV_SMEM = (64 * AS_LD + 64 * 128) * 4;   // 50176
__global__ __launch_bounds__(256)
void uv_kernel(int l) {
    extern __shared__ float sm[];
    float* As = sm;
    float* Bs = sm + 64 * AS_LD;
    const float* hc = g_h[l & 1];
    int tid = threadIdx.x;
    int nbase = blockIdx.x * 64;

    {
        const float4* s = reinterpret_cast<const float4*>(g_wuv[l]);
        float4* d = reinterpret_cast<float4*>(Bs);
        for (int i = tid; i < 64 * 128 / 4; i += 256) d[i] = s[i];
    }
    {
        int n = tid & 63;
        int c0 = tid >> 6;
        int node = nbase + n;
        bool valid = node < NN;
        int ncl = valid ? node : (NN - 1);
        const float4* hp = reinterpret_cast<const float4*>(hc + (size_t)ncl * HD);
        float4 z = make_float4(0.f, 0.f, 0.f, 0.f);
        #pragma unroll
        for (int c = c0; c < 16; c += 4) {
            float4 v = valid ? hp[c] : z;
            As[(4 * c + 0) * AS_LD + n] = v.x;
            As[(4 * c + 1) * AS_LD + n] = v.y;
            As[(4 * c + 2) * AS_LD + n] = v.z;
            As[(4 * c + 3) * AS_LD + n] = v.w;
        }
    }
    __syncthreads();

    int tx4 = (tid & 15) * 4;
    int ty4 = (tid >> 4) * 4;
    unsigned long long acu[4][2] = {}, acv[4][2] = {};
    #pragma unroll 4
    for (int k = 0; k < 64; ++k)
        GEMM_STEP2(acu, acv, As + k * AS_LD + tx4, Bs + k * 128 + ty4, Bs + k * 128 + 64 + ty4);

    #pragma unroll
    for (int i = 0; i < 4; i++) {
        int node = nbase + tx4 + i;
        if (node < NN) {
            float2 u0 = unpk(acu[i][0]), u1 = unpk(acu[i][1]);
            float2 v0 = unpk(acv[i][0]), v1 = unpk(acv[i][1]);
            *reinterpret_cast<float4*>(g_uv + (size_t)node * 128 + ty4)      = make_float4(u0.x, u0.y, u1.x, u1.y);
            *reinterpret_cast<float4*>(g_uv + (size_t)node * 128 + 64 + ty4) = make_float4(v0.x, v0.y, v1.x, v1.y);
        }
    }
}

// ---------------- edge gather (CSR segment sum, warp-staged indices) ----------------
// one warp per dst node; src indices for up to 32 edges loaded coalesced, broadcast by shfl;
// u rows prefetched 2 deep (no in-loop dependent index load)
__global__ __launch_bounds__(256)
void edge_gather(int l) {
    int g = blockIdx.x * 256 + threadIdx.x;
    int w = g >> 5;
    int lane = g & 31;
    if (w >= NN) return;
    int c2 = lane * 2;

    const float* wf = g_wfold[l];
    float2 w0 = *reinterpret_cast<const float2*>(wf + c2);
    float2 w1 = *reinterpret_cast<const float2*>(wf + 64 + c2);
    float2 w2 = *reinterpret_cast<const float2*>(wf + 128 + c2);
    float2 b  = *reinterpret_cast<const float2*>(g_b1eff[l] + c2);
    float2 vv = *reinterpret_cast<const float2*>(g_uv + (size_t)w * 128 + 64 + c2);
    float bx = vv.x + b.x, by = vv.y + b.y;

    int beg = g_rowptr[w];
    int end = g_rowptr[w + 1];
    float ax = 0.f, ay = 0.f;

    for (int c0 = beg; c0 < end; c0 += 32) {
        int n = min(32, end - c0);
        // coalesced stage of up to 32 src indices
        int my_src = (lane < n) ? g_src_s[c0 + lane] : 0;

        // 2-deep pipeline over u rows + evec
        float2 u0, u1;
        float4 e0, e1;
        {
            int s0 = __shfl_sync(0xffffffffu, my_src, 0);
            u0 = *reinterpret_cast<const float2*>(g_uv + (size_t)s0 * 128 + c2);
            e0 = g_evec_s[c0];
        }
        if (n > 1) {
            int s1 = __shfl_sync(0xffffffffu, my_src, 1);
            u1 = *reinterpret_cast<const float2*>(g_uv + (size_t)s1 * 128 + c2);
            e1 = g_evec_s[c0 + 1];
        }
        for (int j = 0; j < n; j++) {
            float2 uu = u0;
            float4 ev = e0;
            u0 = u1;
            e0 = e1;
            if (j + 2 < n) {
                int s2 = __shfl_sync(0xffffffffu, my_src, j + 2);
                u1 = *reinterpret_cast<const float2*>(g_uv + (size_t)s2 * 128 + c2);
                e1 = g_evec_s[c0 + j + 2];
            }
            float p0 = fmaf(ev.x, w0.x, fmaf(ev.y, w1.x, fmaf(ev.z, w2.x, uu.x + bx)));
            float p1 = fmaf(ev.x, w0.y, fmaf(ev.y, w1.y, fmaf(ev.z, w2.y, uu.y + by)));
            ax += fmaxf(p0, 0.f);
            ay += fmaxf(p1, 0.f);
        }
    }
    *reinterpret_cast<float2*>(g_S + (size_t)w * HD + c2) = make_float2(ax, ay);
}

// ---------------- node MLP (fused agg) ----------------
static constexpr int NODE_SMEM = (128 * AS_LD + 128 * 64 + 64 * 64 + 64 + 64) * 4;  // 84480
__global__ __launch_bounds__(256, 2)
void node_kernel(const float* __restrict__ nb1, const float* __restrict__ nw2,
                 const float* __restrict__ nb2, int l) {
    extern __shared__ float sm[];
    float* As  = sm;
    float* W1s = sm + 128 * AS_LD;
    float* W2s = W1s + 128 * 64;
    float* qs  = W2s + 64 * 64;
    float* Dg  = qs + 64;

    const float* hc = g_h[l & 1];
    float* hn = g_h[(l + 1) & 1];
    int tid = threadIdx.x;
    int nbase = blockIdx.x * 64;

    {
        const float4* s1 = reinterpret_cast<const float4*>(g_nwf[l]);
        float4* d1 = reinterpret_cast<float4*>(W1s);
        for (int i = tid; i < 128 * 64 / 4; i += 256) d1[i] = s1[i];
        const float4* s2 = reinterpret_cast<const float4*>(nw2 + (size_t)l * 64 * 64);
        float4* d2 = reinterpret_cast<float4*>(W2s);
        for (int i = tid; i < 64 * 64 / 4; i += 256) d2[i] = s2[i];
        if (tid < 64) {
            qs[tid] = g_q[l][tid];
            int node = nbase + tid;
            Dg[tid] = (node < NN) ? (float)(g_rowptr[node + 1] - g_rowptr[node]) : 0.f;
        }
    }

    {
        int n = tid & 63;
        int c0 = tid >> 6;
        int node = nbase + n;
        bool valid = node < NN;
        int ncl = valid ? node : (NN - 1);
        const float4* hp = reinterpret_cast<const float4*>(hc + (size_t)ncl * HD);
        const float4* ap = reinterpret_cast<const float4*>(g_S + (size_t)ncl * HD);
        float4 z = make_float4(0.f, 0.f, 0.f, 0.f);
        #pragma unroll
        for (int c = c0; c < 16; c += 4) {
            float4 v = valid ? hp[c] : z;
            As[(4 * c + 0) * AS_LD + n] = v.x;
            As[(4 * c + 1) * AS_LD + n] = v.y;
            As[(4 * c + 2) * AS_LD + n] = v.z;
            As[(4 * c + 3) * AS_LD + n] = v.w;
            float4 w = valid ? ap[c] : z;
            As[(64 + 4 * c + 0) * AS_LD + n] = w.x;
            As[(64 + 4 * c + 1) * AS_LD + n] = w.y;
            As[(64 + 4 * c + 2) * AS_LD + n] = w.z;
            As[(64 + 4 * c + 3) * AS_LD + n] = w.w;
        }
    }
    __syncthreads();

    int tx4 = (tid & 15) * 4;
    int ty4 = (tid >> 4) * 4;

    unsigned long long acc[4][2] = {};
    #pragma unroll 4
    for (int k = 0; k < 128; ++k)
        GEMM_STEP(acc, As + k * AS_LD + tx4, W1s + k * 64 + ty4);

    float hid[4][4];
    {
        float2 bA = *reinterpret_cast<const float2*>(nb1 + (size_t)l * 64 + ty4);
        float2 bB = *reinterpret_cast<const float2*>(nb1 + (size_t)l * 64 + ty4 + 2);
        float2 qA = *reinterpret_cast<const float2*>(qs + ty4);
        float2 qB = *reinterpret_cast<const float2*>(qs + ty4 + 2);
        #pragma unroll
        for (int i = 0; i < 4; i++) {
            float dg = Dg[tx4 + i];
            float2 u = unpk(acc[i][0]);
            float2 v = unpk(acc[i][1]);
            hid[i][0] = fmaxf(fmaf(dg, qA.x, u.x + bA.x), 0.f);
            hid[i][1] = fmaxf(fmaf(dg, qA.y, u.y + bA.y), 0.f);
            hid[i][2] = fmaxf(fmaf(dg, qB.x, v.x + bB.x), 0.f);
            hid[i][3] = fmaxf(fmaf(dg, qB.y, v.y + bB.y), 0.f);
        }
    }
    __syncthreads();
    float* Hs = As;
    #pragma unroll
    for (int j = 0; j < 4; j++)
        *reinterpret_cast<float4*>(Hs + (ty4 + j) * AS_LD + tx4) =
            make_float4(hid[0][j], hid[1][j], hid[2][j], hid[3][j]);
    __syncthreads();

    unsigned long long acc2[4][2] = {};
    #pragma unroll 4
    for (int k = 0; k < 64; ++k)
        GEMM_STEP(acc2, Hs + k * AS_LD + tx4, W2s + k * 64 + ty4);

    float2 bA = *reinterpret_cast<const float2*>(nb2 + (size_t)l * 64 + ty4);
    float2 bB = *reinterpret_cast<const float2*>(nb2 + (size_t)l * 64 + ty4 + 2);
    #pragma unroll
    for (int i = 0; i < 4; i++) {
        int node = nbase + tx4 + i;
        if (node < NN) {
            float2 u = unpk(acc2[i][0]);
            float2 v = unpk(acc2[i][1]);
            *reinterpret_cast<float4*>(hn + (size_t)node * HD + ty4) =
                make_float4(u.x + bA.x, u.y + bA.y, v.x + bB.x, v.y + bB.y);
        }
    }
}

// ---------------- decoder ----------------
__global__ void decoder(const float* __restrict__ dw, const float* __restrict__ db,
                        float* __restrict__ out) {
    int gid = blockIdx.x * 256 + threadIdx.x;
    int w = gid >> 5, lane = gid & 31;
    if (w >= NN) return;
    const float* hr = g_h[0] + (size_t)w * HD;
    float v = hr[lane] * dw[lane] + hr[lane + 32] * dw[lane + 32];
    #pragma unroll
    for (int o = 16; o > 0; o >>= 1) v += __shfl_down_sync(0xffffffffu, v, o);
    if (lane == 0) out[w] = v + db[0];
}

// ---------------- launch ----------------
#define NTILES ((NN + 63) / 64)   // 782

extern "C" void kernel_launch(void* const* d_in, const int* in_sizes, int n_in,
                              void* d_out, int out_size) {
    const float* node_pos  = (const float*)d_in[0];
    const float* node_feat = (const float*)d_in[1];
    const int*   eidx      = (const int*)d_in[2];
    const float* enc_w = (const float*)d_in[3];
    const float* enc_b = (const float*)d_in[4];
    const float* eew   = (const float*)d_in[5];
    const float* eeb   = (const float*)d_in[6];
    const float* ew1   = (const float*)d_in[7];
    const float* eb1   = (const float*)d_in[8];
    const float* ew2   = (const float*)d_in[9];
    const float* eb2   = (const float*)d_in[10];
    const float* nw1   = (const float*)d_in[11];
    const float* nb1   = (const float*)d_in[12];
    const float* nw2   = (const float*)d_in[13];
    const float* nb2   = (const float*)d_in[14];
    const float* dec_w = (const float*)d_in[15];
    const float* dec_b = (const float*)d_in[16];
    float* out = (float*)d_out;

    cudaFuncSetAttribute(uv_kernel, cudaFuncAttributeMaxDynamicSharedMemorySize, UV_SMEM);
    cudaFuncSetAttribute(node_kernel, cudaFuncAttributeMaxDynamicSharedMemorySize, NODE_SMEM);

    zero_counters<<<(NN + 255) / 256, 256>>>();
    prep_cnt<<<(NE + 255) / 256, 256>>>(eidx);
    scan_counts<<<1, 1024>>>();
    fill_csr<<<(NE + 255) / 256, 256>>>(eidx, node_pos);
    prep_weights<<<(PREPW_TOT + 255) / 256, 256>>>(ew1, eew, eeb, eb1, eb2, nw1, ew2);
    encoder<<<(NN * HD + 255) / 256, 256>>>(node_feat, enc_w, enc_b);

    for (int l = 0; l < NL; ++l) {
        uv_kernel<<<NTILES, 256, UV_SMEM>>>(l);
        edge_gather<<<(NN * 32 + 255) / 256, 256>>>(l);
        node_kernel<<<NTILES, 256, NODE_SMEM>>>(nb1, nw2, nb2, l);
    }

    decoder<<<(NN * 32 + 255) / 256, 256>>>(dec_w, dec_b, out);
}

// round 13
// speedup vs baseline: 1.1739x; 1.1739x over previous
#include <cuda_runtime.h>

#define NN 50000
#define NE 800000
#define HD 64
#define NL 4
#define AS_LD 68     // uv_kernel A-tile stride (legacy, works)
#define NLD 64       // node kernel A/Hs stride

// ---------------- device scratch ----------------
__device__ __align__(16) float g_h[2][(size_t)NN * HD];
__device__ __align__(16) float g_S[(size_t)NN * HD];        // segment-summed relu(pre1) per node
__device__ __align__(16) float g_uv[(size_t)NN * 128];      // u (cols 0-63), v (cols 64-127)
// CSR (sorted by dst)
__device__ __align__(16) int   g_cnt[NN];
__device__ __align__(16) int   g_fill[NN];
__device__ __align__(16) int   g_rowptr[NN + 1];
__device__ __align__(16) int   g_src_s[NE];
__device__ __align__(16) float4 g_evec_s[NE];
// folded weights
__device__ __align__(16) float g_wfold[NL][3 * 64];         // edge_enc_w @ W1_e
__device__ __align__(16) float g_b1eff[NL][64];             // b1 + eeb @ W1_e
__device__ __align__(16) float g_wuv[NL][64 * 128];         // [W1a | W1b]
__device__ __align__(16) float g_nwf[NL][128 * 64];         // [M1_top ; W2 @ M1_bot]
__device__ __align__(16) float g_q[NL][64];                 // b2 @ M1_bot
__device__ __align__(16) float g_nw23[NL][64 * 192];        // [nw2 | nw2 @ wuv_next]
__device__ __align__(16) float g_quv[3][128];               // nb2 @ wuv_next

// ---------------- f32x2 packed-FMA helpers ----------------
__device__ __forceinline__ void ffma2(unsigned long long& d, unsigned long long a, unsigned long long b) {
    asm("fma.rn.f32x2 %0, %1, %2, %0;" : "+l"(d) : "l"(a), "l"(b));
}
__device__ __forceinline__ unsigned long long splat2(float x) {
    unsigned long long r; asm("mov.b64 %0, {%1, %1};" : "=l"(r) : "f"(x)); return r;
}
__device__ __forceinline__ float2 unpk(unsigned long long v) {
    float2 f; asm("mov.b64 {%0, %1}, %2;" : "=f"(f.x), "=f"(f.y) : "l"(v)); return f;
}

#define GEMM_STEP(ACC, APTR, BPTR) do {                                        \
    float4 a4_ = *reinterpret_cast<const float4*>(APTR);                        \
    ulonglong2 bb_ = *reinterpret_cast<const ulonglong2*>(BPTR);                \
    unsigned long long s_;                                                      \
    s_ = splat2(a4_.x); ffma2(ACC[0][0], s_, bb_.x); ffma2(ACC[0][1], s_, bb_.y); \
    s_ = splat2(a4_.y); ffma2(ACC[1][0], s_, bb_.x); ffma2(ACC[1][1], s_, bb_.y); \
    s_ = splat2(a4_.z); ffma2(ACC[2][0], s_, bb_.x); ffma2(ACC[2][1], s_, bb_.y); \
    s_ = splat2(a4_.w); ffma2(ACC[3][0], s_, bb_.x); ffma2(ACC[3][1], s_, bb_.y); \
} while (0)

#define GEMM_STEP2(ACU, ACV, APTR, BU, BV) do {                                \
    float4 a4_ = *reinterpret_cast<const float4*>(APTR);                        \
    ulonglong2 bu_ = *reinterpret_cast<const ulonglong2*>(BU);                  \
    ulonglong2 bv_ = *reinterpret_cast<const ulonglong2*>(BV);                  \
    unsigned long long s_;                                                      \
    s_ = splat2(a4_.x); ffma2(ACU[0][0], s_, bu_.x); ffma2(ACU[0][1], s_, bu_.y); ffma2(ACV[0][0], s_, bv_.x); ffma2(ACV[0][1], s_, bv_.y); \
    s_ = splat2(a4_.y); ffma2(ACU[1][0], s_, bu_.x); ffma2(ACU[1][1], s_, bu_.y); ffma2(ACV[1][0], s_, bv_.x); ffma2(ACV[1][1], s_, bv_.y); \
    s_ = splat2(a4_.z); ffma2(ACU[2][0], s_, bu_.x); ffma2(ACU[2][1], s_, bu_.y); ffma2(ACV[2][0], s_, bv_.x); ffma2(ACV[2][1], s_, bv_.y); \
    s_ = splat2(a4_.w); ffma2(ACU[3][0], s_, bu_.x); ffma2(ACU[3][1], s_, bu_.y); ffma2(ACV[3][0], s_, bv_.x); ffma2(ACV[3][1], s_, bv_.y); \
} while (0)

// 3-panel variant: one A load + 4 splats feeding 24 FFMA2
#define GEMM_STEP3(A0, A1, A2, APTR, B0, B1, B2) do {                          \
    float4 a4_ = *reinterpret_cast<const float4*>(APTR);                        \
    ulonglong2 b0_ = *reinterpret_cast<const ulonglong2*>(B0);                  \
    ulonglong2 b1_ = *reinterpret_cast<const ulonglong2*>(B1);                  \
    ulonglong2 b2_ = *reinterpret_cast<const ulonglong2*>(B2);                  \
    unsigned long long s_;                                                      \
    s_ = splat2(a4_.x); ffma2(A0[0][0],s_,b0_.x); ffma2(A0[0][1],s_,b0_.y); ffma2(A1[0][0],s_,b1_.x); ffma2(A1[0][1],s_,b1_.y); ffma2(A2[0][0],s_,b2_.x); ffma2(A2[0][1],s_,b2_.y); \
    s_ = splat2(a4_.y); ffma2(A0[1][0],s_,b0_.x); ffma2(A0[1][1],s_,b0_.y); ffma2(A1[1][0],s_,b1_.x); ffma2(A1[1][1],s_,b1_.y); ffma2(A2[1][0],s_,b2_.x); ffma2(A2[1][1],s_,b2_.y); \
    s_ = splat2(a4_.z); ffma2(A0[2][0],s_,b0_.x); ffma2(A0[2][1],s_,b0_.y); ffma2(A1[2][0],s_,b1_.x); ffma2(A1[2][1],s_,b1_.y); ffma2(A2[2][0],s_,b2_.x); ffma2(A2[2][1],s_,b2_.y); \
    s_ = splat2(a4_.w); ffma2(A0[3][0],s_,b0_.x); ffma2(A0[3][1],s_,b0_.y); ffma2(A1[3][0],s_,b1_.x); ffma2(A1[3][1],s_,b1_.y); ffma2(A2[3][0],s_,b2_.x); ffma2(A2[3][1],s_,b2_.y); \
} while (0)

// ---------------- CSR build (no intermediates) ----------------
__global__ void zero_counters() {
    int i = blockIdx.x * 256 + threadIdx.x;
    if (i < NN) { g_cnt[i] = 0; g_fill[i] = 0; }
}

__global__ void prep_cnt(const int* __restrict__ ei) {
    int i = blockIdx.x * 256 + threadIdx.x;
    if (i >= NE) return;
    int d = min(max(ei[NE + i], 0), NN - 1);
    atomicAdd(&g_cnt[d], 1);
}

#define SCN_C 49   // ceil(50000/1024)
__global__ void scan_counts() {
    __shared__ int part[1024];
    int t = threadIdx.x;
    int base = t * SCN_C;
    int sum = 0;
    for (int i = 0; i < SCN_C; i++) {
        int idx = base + i;
        if (idx < NN) sum += g_cnt[idx];
    }
    part[t] = sum;
    __syncthreads();
    for (int off = 1; off < 1024; off <<= 1) {
        int v = (t >= off) ? part[t - off] : 0;
        __syncthreads();
        if (t >= off) part[t] += v;
        __syncthreads();
    }
    int run = (t > 0) ? part[t - 1] : 0;
    for (int i = 0; i < SCN_C; i++) {
        int idx = base + i;
        if (idx < NN) { g_rowptr[idx] = run; run += g_cnt[idx]; }
    }
    if (t == 1023) g_rowptr[NN] = run;
}

__global__ void fill_csr(const int* __restrict__ ei, const float* __restrict__ pos) {
    int i = blockIdx.x * 256 + threadIdx.x;
    if (i >= NE) return;
    int s = min(max(ei[i], 0), NN - 1);
    int d = min(max(ei[NE + i], 0), NN - 1);
    int p = g_rowptr[d] + atomicAdd(&g_fill[d], 1);
    const float* ps = pos + 3 * (size_t)s;
    const float* pd = pos + 3 * (size_t)d;
    g_src_s[p] = s;
    g_evec_s[p] = make_float4(pd[0] - ps[0], pd[1] - ps[1], pd[2] - ps[2], 0.f);
}

// ---------------- combined weight prep ----------------
// helper: wuv[l][m][j] read straight from ew1 (avoids intra-grid dependency)
__device__ __forceinline__ float wuv_src(const float* ew1, int l, int m, int j) {
    const float* base = ew1 + (size_t)l * 192 * 64;
    return (j < 64) ? base[m * 64 + j] : base[(64 + m) * 64 + (j - 64)];
}

#define R1 768
#define R2 1024
#define R3 1280
#define R4 (R3 + NL * 8192)          // 34048
#define R5 (R4 + NL * 8192)          // 66816
#define R6 (R5 + NL * 4096)          // 83200  (nw23 copy part)
#define R7 (R6 + 3 * 8192)           // 107776 (nw23 fused part)
#define PREPW_TOT (R7 + 3 * 128)     // 108160

__global__ void prep_weights(const float* __restrict__ ew1, const float* __restrict__ eew,
                             const float* __restrict__ eeb, const float* __restrict__ eb1,
                             const float* __restrict__ eb2, const float* __restrict__ nw1,
                             const float* __restrict__ ew2, const float* __restrict__ nw2,
                             const float* __restrict__ nb2) {
    int idx = blockIdx.x * 256 + threadIdx.x;
    if (idx >= PREPW_TOT) return;
    if (idx < R1) {
        int j = idx & 63;
        int c = (idx >> 6) % 3;
        int l = idx / 192;
        const float* w = ew1 + (size_t)l * 192 * 64 + 128 * 64 + j;
        float v = 0.f;
        #pragma unroll 8
        for (int m = 0; m < 64; m++) v += eew[c * 64 + m] * w[(size_t)m * 64];
        g_wfold[l][c * 64 + j] = v;
    } else if (idx < R2) {
        int r = idx - R1;
        int j = r & 63;
        int l = r >> 6;
        float v = eb1[l * 64 + j];
        const float* w = ew1 + (size_t)l * 192 * 64 + 128 * 64 + j;
        #pragma unroll 8
        for (int m = 0; m < 64; m++) v += eeb[m] * w[(size_t)m * 64];
        g_b1eff[l][j] = v;
    } else if (idx < R3) {
        int r = idx - R2;
        int j = r & 63;
        int l = r >> 6;
        const float* m1 = nw1 + (size_t)l * 128 * 64;
        float v = 0.f;
        #pragma unroll 8
        for (int m = 0; m < 64; m++) v += eb2[l * 64 + m] * m1[(64 + m) * 64 + j];
        g_q[l][j] = v;
    } else if (idx < R4) {
        int r = idx - R3;
        int j = r & 127;
        int k = (r >> 7) & 63;
        int l = r >> 13;
        g_wuv[l][k * 128 + j] = wuv_src(ew1, l, k, j);
    } else if (idx < R5) {
        int r = idx - R4;
        int j = r & 63;
        int k = (r >> 6) & 127;
        int l = r >> 13;
        const float* m1 = nw1 + (size_t)l * 128 * 64;
        float v;
        if (k < 64) {
            v = m1[k * 64 + j];
        } else {
            int p = k - 64;
            const float* w2 = ew2 + (size_t)l * 64 * 64 + p * 64;
            v = 0.f;
            #pragma unroll 8
            for (int m = 0; m < 64; m++) v += w2[m] * m1[(64 + m) * 64 + j];
        }
        g_nwf[l][k * 64 + j] = v;
    } else if (idx < R6) {
        // nw23 cols 0..63 = nw2
        int r = idx - R5;
        int j = r & 63;
        int k = (r >> 6) & 63;
        int l = r >> 12;
        g_nw23[l][k * 192 + j] = nw2[(size_t)l * 4096 + k * 64 + j];
    } else if (idx < R7) {
        // nw23 cols 64..191 = nw2[l] @ wuv[l+1]  (l = 0..2)
        int r = idx - R6;
        int j = r & 127;
        int k = (r >> 7) & 63;
        int l = r >> 13;
        const float* w2r = nw2 + (size_t)l * 4096 + k * 64;
        float v = 0.f;
        #pragma unroll 8
        for (int m = 0; m < 64; m++) v += w2r[m] * wuv_src(ew1, l + 1, m, j);
        g_nw23[l][k * 192 + 64 + j] = v;
    } else {
        // quv[l][j] = nb2[l] @ wuv[l+1]  (l = 0..2)
        int r = idx - R7;
        int j = r & 127;
        int l = r >> 7;
        float v = 0.f;
        #pragma unroll 8
        for (int m = 0; m < 64; m++) v += nb2[l * 64 + m] * wuv_src(ew1, l + 1, m, j);
        g_quv[l][j] = v;
    }
}

__global__ void encoder(const float* __restrict__ nf, const float* __restrict__ w,
                        const float* __restrict__ b) {
    int idx = blockIdx.x * 256 + threadIdx.x;
    if (idx >= NN * HD) return;
    int j = idx & 63;
    int n = idx >> 6;
    float acc = b[j];
    acc += nf[n * 3 + 0] * w[j] + nf[n * 3 + 1] * w[64 + j] + nf[n * 3 + 2] * w[128 + j];
    g_h[0][idx] = acc;
}

// ---------------- uv kernel (layer 0 only): uv[n] = h[n] @ [W1a|W1b] ----------------
static constexpr int UV_SMEM = (64 * AS_LD + 64 * 128) * 4;   // 50176
__global__ __launch_bounds__(256)
void uv_kernel(int l) {
    extern __shared__ float sm[];
    float* As = sm;
    float* Bs = sm + 64 * AS_LD;
    const float* hc = g_h[l & 1];
    int tid = threadIdx.x;
    int nbase = blockIdx.x * 64;

    {
        const float4* s = reinterpret_cast<const float4*>(g_wuv[l]);
        float4* d = reinterpret_cast<float4*>(Bs);
        for (int i = tid; i < 64 * 128 / 4; i += 256) d[i] = s[i];
    }
    {
        int n = tid & 63;
        int c0 = tid >> 6;
        int node = nbase + n;
        bool valid = node < NN;
        int ncl = valid ? node : (NN - 1);
        const float4* hp = reinterpret_cast<const float4*>(hc + (size_t)ncl * HD);
        float4 z = make_float4(0.f, 0.f, 0.f, 0.f);
        #pragma unroll
        for (int c = c0; c < 16; c += 4) {
            float4 v = valid ? hp[c] : z;
            As[(4 * c + 0) * AS_LD + n] = v.x;
            As[(4 * c + 1) * AS_LD + n] = v.y;
            As[(4 * c + 2) * AS_LD + n] = v.z;
            As[(4 * c + 3) * AS_LD + n] = v.w;
        }
    }
    __syncthreads();

    int tx4 = (tid & 15) * 4;
    int ty4 = (tid >> 4) * 4;
    unsigned long long acu[4][2] = {}, acv[4][2] = {};
    #pragma unroll 4
    for (int k = 0; k < 64; ++k)
        GEMM_STEP2(acu, acv, As + k * AS_LD + tx4, Bs + k * 128 + ty4, Bs + k * 128 + 64 + ty4);

    #pragma unroll
    for (int i = 0; i < 4; i++) {
        int node = nbase + tx4 + i;
        if (node < NN) {
            float2 u0 = unpk(acu[i][0]), u1 = unpk(acu[i][1]);
            float2 v0 = unpk(acv[i][0]), v1 = unpk(acv[i][1]);
            *reinterpret_cast<float4*>(g_uv + (size_t)node * 128 + ty4)      = make_float4(u0.x, u0.y, u1.x, u1.y);
            *reinterpret_cast<float4*>(g_uv + (size_t)node * 128 + 64 + ty4) = make_float4(v0.x, v0.y, v1.x, v1.y);
        }
    }
}

// ---------------- edge gather (CSR segment sum) — R11 form (reverted) ----------------
__global__ __launch_bounds__(256)
void edge_gather(int l) {
    int g = blockIdx.x * 256 + threadIdx.x;
    int w = g >> 5;
    int lane = g & 31;
    if (w >= NN) return;
    int c2 = lane * 2;

    const float* wf = g_wfold[l];
    float2 w0 = *reinterpret_cast<const float2*>(wf + c2);
    float2 w1 = *reinterpret_cast<const float2*>(wf + 64 + c2);
    float2 w2 = *reinterpret_cast<const float2*>(wf + 128 + c2);
    float2 b  = *reinterpret_cast<const float2*>(g_b1eff[l] + c2);
    float2 vv = *reinterpret_cast<const float2*>(g_uv + (size_t)w * 128 + 64 + c2);
    float bx = vv.x + b.x, by = vv.y + b.y;

    int beg = g_rowptr[w];
    int end = g_rowptr[w + 1];
    float ax = 0.f, ay = 0.f;

    float4 ev_c;
    float2 uu_c;
    if (beg < end) {
        int s0 = g_src_s[beg];
        ev_c = g_evec_s[beg];
        uu_c = *reinterpret_cast<const float2*>(g_uv + (size_t)s0 * 128 + c2);
    }
    for (int i = beg; i < end; i++) {
        float4 ev = ev_c;
        float2 uu = uu_c;
        if (i + 1 < end) {
            int sn = g_src_s[i + 1];
            ev_c = g_evec_s[i + 1];
            uu_c = *reinterpret_cast<const float2*>(g_uv + (size_t)sn * 128 + c2);
        }
        float p0 = fmaf(ev.x, w0.x, fmaf(ev.y, w1.x, fmaf(ev.z, w2.x, uu.x + bx)));
        float p1 = fmaf(ev.x, w0.y, fmaf(ev.y, w1.y, fmaf(ev.z, w2.y, uu.y + by)));
        ax += fmaxf(p0, 0.f);
        ay += fmaxf(p1, 0.f);
    }
    *reinterpret_cast<float2*>(g_S + (size_t)w * HD + c2) = make_float2(ax, ay);
}

// ---------------- fused node MLP: hn AND uv_next in one kernel ----------------
// GEMM1: [h|S](K=128) @ nwf -> relu -> Hs ; GEMM2: Hs(K=64) @ [nw2 | nw2@wuv_next](N=192)
static constexpr int NODE_SMEM = (128 * NLD + 128 * 64 + 64 * 192) * 4;  // 114688
template <bool LAST>
__global__ __launch_bounds__(256, 2)
void node_fused(const float* __restrict__ nb1, const float* __restrict__ nb2, int l) {
    extern __shared__ float sm[];
    float* As   = sm;                    // 128 x NLD
    float* W1s  = sm + 128 * NLD;        // 128 x 64
    float* W23s = W1s + 128 * 64;        // 64 x 192
    __shared__ float Dg[64];

    const float* hc = g_h[l & 1];
    float* hn = g_h[(l + 1) & 1];
    int tid = threadIdx.x;
    int nbase = blockIdx.x * 64;

    {
        const float4* s1 = reinterpret_cast<const float4*>(g_nwf[l]);
        float4* d1 = reinterpret_cast<float4*>(W1s);
        for (int i = tid; i < 128 * 64 / 4; i += 256) d1[i] = s1[i];
        constexpr int NC4 = LAST ? 16 : 48;   // float4s per row to stage
        for (int i = tid; i < 64 * NC4; i += 256) {
            int row = i / NC4;
            int c4 = (i % NC4) * 4;
            *reinterpret_cast<float4*>(W23s + row * 192 + c4) =
                *reinterpret_cast<const float4*>(g_nw23[l] + row * 192 + c4);
        }
        if (tid < 64) {
            int node = nbase + tid;
            Dg[tid] = (node < NN) ? (float)(g_rowptr[node + 1] - g_rowptr[node]) : 0.f;
        }
    }

    {
        int n = tid & 63;
        int c0 = tid >> 6;
        int node = nbase + n;
        bool valid = node < NN;
        int ncl = valid ? node : (NN - 1);
        const float4* hp = reinterpret_cast<const float4*>(hc + (size_t)ncl * HD);
        const float4* ap = reinterpret_cast<const float4*>(g_S + (size_t)ncl * HD);
        float4 z = make_float4(0.f, 0.f, 0.f, 0.f);
        #pragma unroll
        for (int c = c0; c < 16; c += 4) {
            float4 v = valid ? hp[c] : z;
            As[(4 * c + 0) * NLD + n] = v.x;
            As[(4 * c + 1) * NLD + n] = v.y;
            As[(4 * c + 2) * NLD + n] = v.z;
            As[(4 * c + 3) * NLD + n] = v.w;
            float4 w = valid ? ap[c] : z;
            As[(64 + 4 * c + 0) * NLD + n] = w.x;
            As[(64 + 4 * c + 1) * NLD + n] = w.y;
            As[(64 + 4 * c + 2) * NLD + n] = w.z;
            As[(64 + 4 * c + 3) * NLD + n] = w.w;
        }
    }
    __syncthreads();

    int tx4 = (tid & 15) * 4;
    int ty4 = (tid >> 4) * 4;

    unsigned long long acc[4][2] = {};
    #pragma unroll 4
    for (int k = 0; k < 128; ++k)
        GEMM_STEP(acc, As + k * NLD + tx4, W1s + k * 64 + ty4);

    float hid[4][4];
    {
        float2 bA = *reinterpret_cast<const float2*>(nb1 + (size_t)l * 64 + ty4);
        float2 bB = *reinterpret_cast<const float2*>(nb1 + (size_t)l * 64 + ty4 + 2);
        float2 qA = *reinterpret_cast<const float2*>(g_q[l] + ty4);
        float2 qB = *reinterpret_cast<const float2*>(g_q[l] + ty4 + 2);
        #pragma unroll
        for (int i = 0; i < 4; i++) {
            float dg = Dg[tx4 + i];
            float2 u = unpk(acc[i][0]);
            float2 v = unpk(acc[i][1]);
            hid[i][0] = fmaxf(fmaf(dg, qA.x, u.x + bA.x), 0.f);
            hid[i][1] = fmaxf(fmaf(dg, qA.y, u.y + bA.y), 0.f);
            hid[i][2] = fmaxf(fmaf(dg, qB.x, v.x + bB.x), 0.f);
            hid[i][3] = fmaxf(fmaf(dg, qB.y, v.y + bB.y), 0.f);
        }
    }
    __syncthreads();
    float* Hs = As;   // overlay: 64 x NLD
    #pragma unroll
    for (int j = 0; j < 4; j++)
        *reinterpret_cast<float4*>(Hs + (ty4 + j) * NLD + tx4) =
            make_float4(hid[0][j], hid[1][j], hid[2][j], hid[3][j]);
    __syncthreads();

    // GEMM2 over N=192 (or 64 for LAST): panels at col offsets 0 / 64 / 128
    unsigned long long a0[4][2] = {}, a1[4][2] = {}, a2[4][2] = {};
    if (LAST) {
        #pragma unroll 4
        for (int k = 0; k < 64; ++k)
            GEMM_STEP(a0, Hs + k * NLD + tx4, W23s + k * 192 + ty4);
    } else {
        #pragma unroll 2
        for (int k = 0; k < 64; ++k)
            GEMM_STEP3(a0, a1, a2, Hs + k * NLD + tx4,
                       W23s + k * 192 + ty4, W23s + k * 192 + 64 + ty4, W23s + k * 192 + 128 + ty4);
    }

    float2 bA = *reinterpret_cast<const float2*>(nb2 + (size_t)l * 64 + ty4);
    float2 bB = *reinterpret_cast<const float2*>(nb2 + (size_t)l * 64 + ty4 + 2);
    float2 qu0, qu1, qv0, qv1;
    if (!LAST) {
        qu0 = *reinterpret_cast<const float2*>(g_quv[l] + ty4);
        qu1 = *reinterpret_cast<const float2*>(g_quv[l] + ty4 + 2);
        qv0 = *reinterpret_cast<const float2*>(g_quv[l] + 64 + ty4);
        qv1 = *reinterpret_cast<const float2*>(g_quv[l] + 64 + ty4 + 2);
    }
    #pragma unroll
    for (int i = 0; i < 4; i++) {
        int node = nbase + tx4 + i;
        if (node < NN) {
            float2 h0 = unpk(a0[i][0]);
            float2 h1 = unpk(a0[i][1]);
            *reinterpret_cast<float4*>(hn + (size_t)node * HD + ty4) =
                make_float4(h0.x + bA.x, h0.y + bA.y, h1.x + bB.x, h1.y + bB.y);
            if (!LAST) {
                float2 u0 = unpk(a1[i][0]), u1 = unpk(a1[i][1]);
                float2 v0 = unpk(a2[i][0]), v1 = unpk(a2[i][1]);
                *reinterpret_cast<float4*>(g_uv + (size_t)node * 128 + ty4) =
                    make_float4(u0.x + qu0.x, u0.y + qu0.y, u1.x + qu1.x, u1.y + qu1.y);
                *reinterpret_cast<float4*>(g_uv + (size_t)node * 128 + 64 + ty4) =
                    make_float4(v0.x + qv0.x, v0.y + qv0.y, v1.x + qv1.x, v1.y + qv1.y);
            }
        }
    }
}

// ---------------- decoder ----------------
__global__ void decoder(const float* __restrict__ dw, const float* __restrict__ db,
                        float* __restrict__ out) {
    int gid = blockIdx.x * 256 + threadIdx.x;
    int w = gid >> 5, lane = gid & 31;
    if (w >= NN) return;
    const float* hr = g_h[0] + (size_t)w * HD;
    float v = hr[lane] * dw[lane] + hr[lane + 32] * dw[lane + 32];
    #pragma unroll
    for (int o = 16; o > 0; o >>= 1) v += __shfl_down_sync(0xffffffffu, v, o);
    if (lane == 0) out[w] = v + db[0];
}

// ---------------- launch ----------------
#define NTILES ((NN + 63) / 64)   // 782

extern "C" void kernel_launch(void* const* d_in, const int* in_sizes, int n_in,
                              void* d_out, int out_size) {
    const float* node_pos  = (const float*)d_in[0];
    const float* node_feat = (const float*)d_in[1];
    const int*   eidx      = (const int*)d_in[2];
    const float* enc_w = (const float*)d_in[3];
    const float* enc_b = (const float*)d_in[4];
    const float* eew   = (const float*)d_in[5];
    const float* eeb   = (const float*)d_in[6];
    const float* ew1   = (const float*)d_in[7];
    const float* eb1   = (const float*)d_in[8];
    const float* ew2   = (const float*)d_in[9];
    const float* eb2   = (const float*)d_in[10];
    const float* nw1   = (const float*)d_in[11];
    const float* nb1   = (const float*)d_in[12];
    const float* nw2   = (const float*)d_in[13];
    const float* nb2   = (const float*)d_in[14];
    const float* dec_w = (const float*)d_in[15];
    const float* dec_b = (const float*)d_in[16];
    float* out = (float*)d_out;

    cudaFuncSetAttribute(uv_kernel, cudaFuncAttributeMaxDynamicSharedMemorySize, UV_SMEM);
    cudaFuncSetAttribute(node_fused<false>, cudaFuncAttributeMaxDynamicSharedMemorySize, NODE_SMEM);
    cudaFuncSetAttribute(node_fused<true>,  cudaFuncAttributeMaxDynamicSharedMemorySize, NODE_SMEM);

    zero_counters<<<(NN + 255) / 256, 256>>>();
    prep_cnt<<<(NE + 255) / 256, 256>>>(eidx);
    scan_counts<<<1, 1024>>>();
    fill_csr<<<(NE + 255) / 256, 256>>>(eidx, node_pos);
    prep_weights<<<(PREPW_TOT + 255) / 256, 256>>>(ew1, eew, eeb, eb1, eb2, nw1, ew2, nw2, nb2);
    encoder<<<(NN * HD + 255) / 256, 256>>>(node_feat, enc_w, enc_b);

    uv_kernel<<<NTILES, 256, UV_SMEM>>>(0);
    for (int l = 0; l < NL; ++l) {
        edge_gather<<<(NN * 32 + 255) / 256, 256>>>(l);
        if (l < NL - 1)
            node_fused<false><<<NTILES, 256, NODE_SMEM>>>(nb1, nb2, l);
        else
            node_fused<true><<<NTILES, 256, NODE_SMEM>>>(nb1, nb2, l);
    }

    decoder<<<(NN * 32 + 255) / 256, 256>>>(dec_w, dec_b, out);
}

// round 14
// speedup vs baseline: 1.1782x; 1.0037x over previous
#include <cuda_runtime.h>

#define NN 50000
#define NE 800000
#define HD 64
#define NL 4
#define AS_LD 68     // uv_kernel A-tile stride (legacy, works)
#define NLD 64       // node kernel A/Hs stride

// ---------------- device scratch ----------------
__device__ __align__(16) float g_h[2][(size_t)NN * HD];
__device__ __align__(16) float g_S[(size_t)NN * HD];        // segment-summed relu(pre1) per node
__device__ __align__(16) float g_uv[(size_t)NN * 128];      // u (cols 0-63), v (cols 64-127)
// CSR (sorted by dst)
__device__ __align__(16) int   g_cnt[NN];
__device__ __align__(16) int   g_fill[NN];
__device__ __align__(16) int   g_rowptr[NN + 1];
__device__ __align__(16) int   g_src_s[NE];
__device__ __align__(16) float4 g_evec_s[NE];
// folded weights
__device__ __align__(16) float g_wfold[NL][3 * 64];         // edge_enc_w @ W1_e
__device__ __align__(16) float g_b1eff[NL][64];             // b1 + eeb @ W1_e
__device__ __align__(16) float g_wuv[NL][64 * 128];         // [W1a | W1b]
__device__ __align__(16) float g_nwf[NL][128 * 64];         // [M1_top ; W2 @ M1_bot]
__device__ __align__(16) float g_q[NL][64];                 // b2 @ M1_bot
__device__ __align__(16) float g_nw23[NL][64 * 192];        // [nw2 | nw2 @ wuv_next]
__device__ __align__(16) float g_quv[3][128];               // nb2 @ wuv_next

// ---------------- f32x2 packed-FMA helpers ----------------
__device__ __forceinline__ void ffma2(unsigned long long& d, unsigned long long a, unsigned long long b) {
    asm("fma.rn.f32x2 %0, %1, %2, %0;" : "+l"(d) : "l"(a), "l"(b));
}
__device__ __forceinline__ unsigned long long splat2(float x) {
    unsigned long long r; asm("mov.b64 %0, {%1, %1};" : "=l"(r) : "f"(x)); return r;
}
__device__ __forceinline__ float2 unpk(unsigned long long v) {
    float2 f; asm("mov.b64 {%0, %1}, %2;" : "=f"(f.x), "=f"(f.y) : "l"(v)); return f;
}

#define GEMM_STEP(ACC, APTR, BPTR) do {                                        \
    float4 a4_ = *reinterpret_cast<const float4*>(APTR);                        \
    ulonglong2 bb_ = *reinterpret_cast<const ulonglong2*>(BPTR);                \
    unsigned long long s_;                                                      \
    s_ = splat2(a4_.x); ffma2(ACC[0][0], s_, bb_.x); ffma2(ACC[0][1], s_, bb_.y); \
    s_ = splat2(a4_.y); ffma2(ACC[1][0], s_, bb_.x); ffma2(ACC[1][1], s_, bb_.y); \
    s_ = splat2(a4_.z); ffma2(ACC[2][0], s_, bb_.x); ffma2(ACC[2][1], s_, bb_.y); \
    s_ = splat2(a4_.w); ffma2(ACC[3][0], s_, bb_.x); ffma2(ACC[3][1], s_, bb_.y); \
} while (0)

#define GEMM_STEP2(ACU, ACV, APTR, BU, BV) do {                                \
    float4 a4_ = *reinterpret_cast<const float4*>(APTR);                        \
    ulonglong2 bu_ = *reinterpret_cast<const ulonglong2*>(BU);                  \
    ulonglong2 bv_ = *reinterpret_cast<const ulonglong2*>(BV);                  \
    unsigned long long s_;                                                      \
    s_ = splat2(a4_.x); ffma2(ACU[0][0], s_, bu_.x); ffma2(ACU[0][1], s_, bu_.y); ffma2(ACV[0][0], s_, bv_.x); ffma2(ACV[0][1], s_, bv_.y); \
    s_ = splat2(a4_.y); ffma2(ACU[1][0], s_, bu_.x); ffma2(ACU[1][1], s_, bu_.y); ffma2(ACV[1][0], s_, bv_.x); ffma2(ACV[1][1], s_, bv_.y); \
    s_ = splat2(a4_.z); ffma2(ACU[2][0], s_, bu_.x); ffma2(ACU[2][1], s_, bu_.y); ffma2(ACV[2][0], s_, bv_.x); ffma2(ACV[2][1], s_, bv_.y); \
    s_ = splat2(a4_.w); ffma2(ACU[3][0], s_, bu_.x); ffma2(ACU[3][1], s_, bu_.y); ffma2(ACV[3][0], s_, bv_.x); ffma2(ACV[3][1], s_, bv_.y); \
} while (0)

// 3-panel variant: one A load + 4 splats feeding 24 FFMA2
#define GEMM_STEP3(A0, A1, A2, APTR, B0, B1, B2) do {                          \
    float4 a4_ = *reinterpret_cast<const float4*>(APTR);                        \
    ulonglong2 b0_ = *reinterpret_cast<const ulonglong2*>(B0);                  \
    ulonglong2 b1_ = *reinterpret_cast<const ulonglong2*>(B1);                  \
    ulonglong2 b2_ = *reinterpret_cast<const ulonglong2*>(B2);                  \
    unsigned long long s_;                                                      \
    s_ = splat2(a4_.x); ffma2(A0[0][0],s_,b0_.x); ffma2(A0[0][1],s_,b0_.y); ffma2(A1[0][0],s_,b1_.x); ffma2(A1[0][1],s_,b1_.y); ffma2(A2[0][0],s_,b2_.x); ffma2(A2[0][1],s_,b2_.y); \
    s_ = splat2(a4_.y); ffma2(A0[1][0],s_,b0_.x); ffma2(A0[1][1],s_,b0_.y); ffma2(A1[1][0],s_,b1_.x); ffma2(A1[1][1],s_,b1_.y); ffma2(A2[1][0],s_,b2_.x); ffma2(A2[1][1],s_,b2_.y); \
    s_ = splat2(a4_.z); ffma2(A0[2][0],s_,b0_.x); ffma2(A0[2][1],s_,b0_.y); ffma2(A1[2][0],s_,b1_.x); ffma2(A1[2][1],s_,b1_.y); ffma2(A2[2][0],s_,b2_.x); ffma2(A2[2][1],s_,b2_.y); \
    s_ = splat2(a4_.w); ffma2(A0[3][0],s_,b0_.x); ffma2(A0[3][1],s_,b0_.y); ffma2(A1[3][0],s_,b1_.x); ffma2(A1[3][1],s_,b1_.y); ffma2(A2[3][0],s_,b2_.x); ffma2(A2[3][1],s_,b2_.y); \
} while (0)

// ---------------- CSR build (no intermediates) ----------------
__global__ void zero_counters() {
    int i = blockIdx.x * 256 + threadIdx.x;
    if (i < NN) { g_cnt[i] = 0; g_fill[i] = 0; }
}

__global__ void prep_cnt(const int* __restrict__ ei) {
    int i = blockIdx.x * 256 + threadIdx.x;
    if (i >= NE) return;
    int d = min(max(ei[NE + i], 0), NN - 1);
    atomicAdd(&g_cnt[d], 1);
}

#define SCN_C 49   // ceil(50000/1024)
__global__ void scan_counts() {
    __shared__ int part[1024];
    int t = threadIdx.x;
    int base = t * SCN_C;
    int sum = 0;
    for (int i = 0; i < SCN_C; i++) {
        int idx = base + i;
        if (idx < NN) sum += g_cnt[idx];
    }
    part[t] = sum;
    __syncthreads();
    for (int off = 1; off < 1024; off <<= 1) {
        int v = (t >= off) ? part[t - off] : 0;
        __syncthreads();
        if (t >= off) part[t] += v;
        __syncthreads();
    }
    int run = (t > 0) ? part[t - 1] : 0;
    for (int i = 0; i < SCN_C; i++) {
        int idx = base + i;
        if (idx < NN) { g_rowptr[idx] = run; run += g_cnt[idx]; }
    }
    if (t == 1023) g_rowptr[NN] = run;
}

__global__ void fill_csr(const int* __restrict__ ei, const float* __restrict__ pos) {
    int i = blockIdx.x * 256 + threadIdx.x;
    if (i >= NE) return;
    int s = min(max(ei[i], 0), NN - 1);
    int d = min(max(ei[NE + i], 0), NN - 1);
    int p = g_rowptr[d] + atomicAdd(&g_fill[d], 1);
    const float* ps = pos + 3 * (size_t)s;
    const float* pd = pos + 3 * (size_t)d;
    g_src_s[p] = s;
    g_evec_s[p] = make_float4(pd[0] - ps[0], pd[1] - ps[1], pd[2] - ps[2], 0.f);
}

// ---------------- combined weight prep ----------------
// helper: wuv[l][m][j] read straight from ew1 (avoids intra-grid dependency)
__device__ __forceinline__ float wuv_src(const float* ew1, int l, int m, int j) {
    const float* base = ew1 + (size_t)l * 192 * 64;
    return (j < 64) ? base[m * 64 + j] : base[(64 + m) * 64 + (j - 64)];
}

#define R1 768
#define R2 1024
#define R3 1280
#define R4 (R3 + NL * 8192)          // 34048
#define R5 (R4 + NL * 8192)          // 66816
#define R6 (R5 + NL * 4096)          // 83200  (nw23 copy part)
#define R7 (R6 + 3 * 8192)           // 107776 (nw23 fused part)
#define PREPW_TOT (R7 + 3 * 128)     // 108160

__global__ void prep_weights(const float* __restrict__ ew1, const float* __restrict__ eew,
                             const float* __restrict__ eeb, const float* __restrict__ eb1,
                             const float* __restrict__ eb2, const float* __restrict__ nw1,
                             const float* __restrict__ ew2, const float* __restrict__ nw2,
                             const float* __restrict__ nb2) {
    int idx = blockIdx.x * 256 + threadIdx.x;
    if (idx >= PREPW_TOT) return;
    if (idx < R1) {
        int j = idx & 63;
        int c = (idx >> 6) % 3;
        int l = idx / 192;
        const float* w = ew1 + (size_t)l * 192 * 64 + 128 * 64 + j;
        float v = 0.f;
        #pragma unroll 8
        for (int m = 0; m < 64; m++) v += eew[c * 64 + m] * w[(size_t)m * 64];
        g_wfold[l][c * 64 + j] = v;
    } else if (idx < R2) {
        int r = idx - R1;
        int j = r & 63;
        int l = r >> 6;
        float v = eb1[l * 64 + j];
        const float* w = ew1 + (size_t)l * 192 * 64 + 128 * 64 + j;
        #pragma unroll 8
        for (int m = 0; m < 64; m++) v += eeb[m] * w[(size_t)m * 64];
        g_b1eff[l][j] = v;
    } else if (idx < R3) {
        int r = idx - R2;
        int j = r & 63;
        int l = r >> 6;
        const float* m1 = nw1 + (size_t)l * 128 * 64;
        float v = 0.f;
        #pragma unroll 8
        for (int m = 0; m < 64; m++) v += eb2[l * 64 + m] * m1[(64 + m) * 64 + j];
        g_q[l][j] = v;
    } else if (idx < R4) {
        int r = idx - R3;
        int j = r & 127;
        int k = (r >> 7) & 63;
        int l = r >> 13;
        g_wuv[l][k * 128 + j] = wuv_src(ew1, l, k, j);
    } else if (idx < R5) {
        int r = idx - R4;
        int j = r & 63;
        int k = (r >> 6) & 127;
        int l = r >> 13;
        const float* m1 = nw1 + (size_t)l * 128 * 64;
        float v;
        if (k < 64) {
            v = m1[k * 64 + j];
        } else {
            int p = k - 64;
            const float* w2 = ew2 + (size_t)l * 64 * 64 + p * 64;
            v = 0.f;
            #pragma unroll 8
            for (int m = 0; m < 64; m++) v += w2[m] * m1[(64 + m) * 64 + j];
        }
        g_nwf[l][k * 64 + j] = v;
    } else if (idx < R6) {
        // nw23 cols 0..63 = nw2
        int r = idx - R5;
        int j = r & 63;
        int k = (r >> 6) & 63;
        int l = r >> 12;
        g_nw23[l][k * 192 + j] = nw2[(size_t)l * 4096 + k * 64 + j];
    } else if (idx < R7) {
        // nw23 cols 64..191 = nw2[l] @ wuv[l+1]  (l = 0..2)
        int r = idx - R6;
        int j = r & 127;
        int k = (r >> 7) & 63;
        int l = r >> 13;
        const float* w2r = nw2 + (size_t)l * 4096 + k * 64;
        float v = 0.f;
        #pragma unroll 8
        for (int m = 0; m < 64; m++) v += w2r[m] * wuv_src(ew1, l + 1, m, j);
        g_nw23[l][k * 192 + 64 + j] = v;
    } else {
        // quv[l][j] = nb2[l] @ wuv[l+1]  (l = 0..2)
        int r = idx - R7;
        int j = r & 127;
        int l = r >> 7;
        float v = 0.f;
        #pragma unroll 8
        for (int m = 0; m < 64; m++) v += nb2[l * 64 + m] * wuv_src(ew1, l + 1, m, j);
        g_quv[l][j] = v;
    }
}

__global__ void encoder(const float* __restrict__ nf, const float* __restrict__ w,
                        const float* __restrict__ b) {
    int idx = blockIdx.x * 256 + threadIdx.x;
    if (idx >= NN * HD) return;
    int j = idx & 63;
    int n = idx >> 6;
    float acc = b[j];
    acc += nf[n * 3 + 0] * w[j] + nf[n * 3 + 1] * w[64 + j] + nf[n * 3 + 2] * w[128 + j];
    g_h[0][idx] = acc;
}

// ---------------- uv kernel (layer 0 only): uv[n] = h[n] @ [W1a|W1b] ----------------
static constexpr int UV_SMEM = (64 * AS_LD + 64 * 128) * 4;   // 50176
__global__ __launch_bounds__(256)
void uv_kernel(int l) {
    extern __shared__ float sm[];
    float* As = sm;
    float* Bs = sm + 64 * AS_LD;
    const float* hc = g_h[l & 1];
    int tid = threadIdx.x;
    int nbase = blockIdx.x * 64;

    {
        const float4* s = reinterpret_cast<const float4*>(g_wuv[l]);
        float4* d = reinterpret_cast<float4*>(Bs);
        for (int i = tid; i < 64 * 128 / 4; i += 256) d[i] = s[i];
    }
    {
        int n = tid & 63;
        int c0 = tid >> 6;
        int node = nbase + n;
        bool valid = node < NN;
        int ncl = valid ? node : (NN - 1);
        const float4* hp = reinterpret_cast<const float4*>(hc + (size_t)ncl * HD);
        float4 z = make_float4(0.f, 0.f, 0.f, 0.f);
        #pragma unroll
        for (int c = c0; c < 16; c += 4) {
            float4 v = valid ? hp[c] : z;
            As[(4 * c + 0) * AS_LD + n] = v.x;
            As[(4 * c + 1) * AS_LD + n] = v.y;
            As[(4 * c + 2) * AS_LD + n] = v.z;
            As[(4 * c + 3) * AS_LD + n] = v.w;
        }
    }
    __syncthreads();

    int tx4 = (tid & 15) * 4;
    int ty4 = (tid >> 4) * 4;
    unsigned long long acu[4][2] = {}, acv[4][2] = {};
    #pragma unroll 4
    for (int k = 0; k < 64; ++k)
        GEMM_STEP2(acu, acv, As + k * AS_LD + tx4, Bs + k * 128 + ty4, Bs + k * 128 + 64 + ty4);

    #pragma unroll
    for (int i = 0; i < 4; i++) {
        int node = nbase + tx4 + i;
        if (node < NN) {
            float2 u0 = unpk(acu[i][0]), u1 = unpk(acu[i][1]);
            float2 v0 = unpk(acv[i][0]), v1 = unpk(acv[i][1]);
            *reinterpret_cast<float4*>(g_uv + (size_t)node * 128 + ty4)      = make_float4(u0.x, u0.y, u1.x, u1.y);
            *reinterpret_cast<float4*>(g_uv + (size_t)node * 128 + 64 + ty4) = make_float4(v0.x, v0.y, v1.x, v1.y);
        }
    }
}

// ---------------- edge gather (CSR segment sum) — R11 form (reverted) ----------------
__global__ __launch_bounds__(256)
void edge_gather(int l) {
    int g = blockIdx.x * 256 + threadIdx.x;
    int w = g >> 5;
    int lane = g & 31;
    if (w >= NN) return;
    int c2 = lane * 2;

    const float* wf = g_wfold[l];
    float2 w0 = *reinterpret_cast<const float2*>(wf + c2);
    float2 w1 = *reinterpret_cast<const float2*>(wf + 64 + c2);
    float2 w2 = *reinterpret_cast<const float2*>(wf + 128 + c2);
    float2 b  = *reinterpret_cast<const float2*>(g_b1eff[l] + c2);
    float2 vv = *reinterpret_cast<const float2*>(g_uv + (size_t)w * 128 + 64 + c2);
    float bx = vv.x + b.x, by = vv.y + b.y;

    int beg = g_rowptr[w];
    int end = g_rowptr[w + 1];
    float ax = 0.f, ay = 0.f;

    float4 ev_c;
    float2 uu_c;
    if (beg < end) {
        int s0 = g_src_s[beg];
        ev_c = g_evec_s[beg];
        uu_c = *reinterpret_cast<const float2*>(g_uv + (size_t)s0 * 128 + c2);
    }
    for (int i = beg; i < end; i++) {
        float4 ev = ev_c;
        float2 uu = uu_c;
        if (i + 1 < end) {
            int sn = g_src_s[i + 1];
            ev_c = g_evec_s[i + 1];
            uu_c = *reinterpret_cast<const float2*>(g_uv + (size_t)sn * 128 + c2);
        }
        float p0 = fmaf(ev.x, w0.x, fmaf(ev.y, w1.x, fmaf(ev.z, w2.x, uu.x + bx)));
        float p1 = fmaf(ev.x, w0.y, fmaf(ev.y, w1.y, fmaf(ev.z, w2.y, uu.y + by)));
        ax += fmaxf(p0, 0.f);
        ay += fmaxf(p1, 0.f);
    }
    *reinterpret_cast<float2*>(g_S + (size_t)w * HD + c2) = make_float2(ax, ay);
}

// ---------------- fused node MLP: hn AND uv_next in one kernel ----------------
// GEMM1: [h|S](K=128) @ nwf -> relu -> Hs ; GEMM2: Hs(K=64) @ [nw2 | nw2@wuv_next](N=192)
static constexpr int NODE_SMEM = (128 * NLD + 128 * 64 + 64 * 192) * 4;  // 114688
template <bool LAST>
__global__ __launch_bounds__(256, 2)
void node_fused(const float* __restrict__ nb1, const float* __restrict__ nb2, int l) {
    extern __shared__ float sm[];
    float* As   = sm;                    // 128 x NLD
    float* W1s  = sm + 128 * NLD;        // 128 x 64
    float* W23s = W1s + 128 * 64;        // 64 x 192
    __shared__ float Dg[64];

    const float* hc = g_h[l & 1];
    float* hn = g_h[(l + 1) & 1];
    int tid = threadIdx.x;
    int nbase = blockIdx.x * 64;

    {
        const float4* s1 = reinterpret_cast<const float4*>(g_nwf[l]);
        float4* d1 = reinterpret_cast<float4*>(W1s);
        for (int i = tid; i < 128 * 64 / 4; i += 256) d1[i] = s1[i];
        constexpr int NC4 = LAST ? 16 : 48;   // float4s per row to stage
        for (int i = tid; i < 64 * NC4; i += 256) {
            int row = i / NC4;
            int c4 = (i % NC4) * 4;
            *reinterpret_cast<float4*>(W23s + row * 192 + c4) =
                *reinterpret_cast<const float4*>(g_nw23[l] + row * 192 + c4);
        }
        if (tid < 64) {
            int node = nbase + tid;
            Dg[tid] = (node < NN) ? (float)(g_rowptr[node + 1] - g_rowptr[node]) : 0.f;
        }
    }

    {
        int n = tid & 63;
        int c0 = tid >> 6;
        int node = nbase + n;
        bool valid = node < NN;
        int ncl = valid ? node : (NN - 1);
        const float4* hp = reinterpret_cast<const float4*>(hc + (size_t)ncl * HD);
        const float4* ap = reinterpret_cast<const float4*>(g_S + (size_t)ncl * HD);
        float4 z = make_float4(0.f, 0.f, 0.f, 0.f);
        #pragma unroll
        for (int c = c0; c < 16; c += 4) {
            float4 v = valid ? hp[c] : z;
            As[(4 * c + 0) * NLD + n] = v.x;
            As[(4 * c + 1) * NLD + n] = v.y;
            As[(4 * c + 2) * NLD + n] = v.z;
            As[(4 * c + 3) * NLD + n] = v.w;
            float4 w = valid ? ap[c] : z;
            As[(64 + 4 * c + 0) * NLD + n] = w.x;
            As[(64 + 4 * c + 1) * NLD + n] = w.y;
            As[(64 + 4 * c + 2) * NLD + n] = w.z;
            As[(64 + 4 * c + 3) * NLD + n] = w.w;
        }
    }
    __syncthreads();

    int tx4 = (tid & 15) * 4;
    int ty4 = (tid >> 4) * 4;

    unsigned long long acc[4][2] = {};
    #pragma unroll 4
    for (int k = 0; k < 128; ++k)
        GEMM_STEP(acc, As + k * NLD + tx4, W1s + k * 64 + ty4);

    float hid[4][4];
    {
        float2 bA = *reinterpret_cast<const float2*>(nb1 + (size_t)l * 64 + ty4);
        float2 bB = *reinterpret_cast<const float2*>(nb1 + (size_t)l * 64 + ty4 + 2);
        float2 qA = *reinterpret_cast<const float2*>(g_q[l] + ty4);
        float2 qB = *reinterpret_cast<const float2*>(g_q[l] + ty4 + 2);
        #pragma unroll
        for (int i = 0; i < 4; i++) {
            float dg = Dg[tx4 + i];
            float2 u = unpk(acc[i][0]);
            float2 v = unpk(acc[i][1]);
            hid[i][0] = fmaxf(fmaf(dg, qA.x, u.x + bA.x), 0.f);
            hid[i][1] = fmaxf(fmaf(dg, qA.y, u.y + bA.y), 0.f);
            hid[i][2] = fmaxf(fmaf(dg, qB.x, v.x + bB.x), 0.f);
            hid[i][3] = fmaxf(fmaf(dg, qB.y, v.y + bB.y), 0.f);
        }
    }
    __syncthreads();
    float* Hs = As;   // overlay: 64 x NLD
    #pragma unroll
    for (int j = 0; j < 4; j++)
        *reinterpret_cast<float4*>(Hs + (ty4 + j) * NLD + tx4) =
            make_float4(hid[0][j], hid[1][j], hid[2][j], hid[3][j]);
    __syncthreads();

    // GEMM2 over N=192 (or 64 for LAST): panels at col offsets 0 / 64 / 128
    unsigned long long a0[4][2] = {}, a1[4][2] = {}, a2[4][2] = {};
    if (LAST) {
        #pragma unroll 4
        for (int k = 0; k < 64; ++k)
            GEMM_STEP(a0, Hs + k * NLD + tx4, W23s + k * 192 + ty4);
    } else {
        #pragma unroll 2
        for (int k = 0; k < 64; ++k)
            GEMM_STEP3(a0, a1, a2, Hs + k * NLD + tx4,
                       W23s + k * 192 + ty4, W23s + k * 192 + 64 + ty4, W23s + k * 192 + 128 + ty4);
    }

    float2 bA = *reinterpret_cast<const float2*>(nb2 + (size_t)l * 64 + ty4);
    float2 bB = *reinterpret_cast<const float2*>(nb2 + (size_t)l * 64 + ty4 + 2);
    float2 qu0, qu1, qv0, qv1;
    if (!LAST) {
        qu0 = *reinterpret_cast<const float2*>(g_quv[l] + ty4);
        qu1 = *reinterpret_cast<const float2*>(g_quv[l] + ty4 + 2);
        qv0 = *reinterpret_cast<const float2*>(g_quv[l] + 64 + ty4);
        qv1 = *reinterpret_cast<const float2*>(g_quv[l] + 64 + ty4 + 2);
    }
    #pragma unroll
    for (int i = 0; i < 4; i++) {
        int node = nbase + tx4 + i;
        if (node < NN) {
            float2 h0 = unpk(a0[i][0]);
            float2 h1 = unpk(a0[i][1]);
            *reinterpret_cast<float4*>(hn + (size_t)node * HD + ty4) =
                make_float4(h0.x + bA.x, h0.y + bA.y, h1.x + bB.x, h1.y + bB.y);
            if (!LAST) {
                float2 u0 = unpk(a1[i][0]), u1 = unpk(a1[i][1]);
                float2 v0 = unpk(a2[i][0]), v1 = unpk(a2[i][1]);
                *reinterpret_cast<float4*>(g_uv + (size_t)node * 128 + ty4) =
                    make_float4(u0.x + qu0.x, u0.y + qu0.y, u1.x + qu1.x, u1.y + qu1.y);
                *reinterpret_cast<float4*>(g_uv + (size_t)node * 128 + 64 + ty4) =
                    make_float4(v0.x + qv0.x, v0.y + qv0.y, v1.x + qv1.x, v1.y + qv1.y);
            }
        }
    }
}

// ---------------- decoder ----------------
__global__ void decoder(const float* __restrict__ dw, const float* __restrict__ db,
                        float* __restrict__ out) {
    int gid = blockIdx.x * 256 + threadIdx.x;
    int w = gid >> 5, lane = gid & 31;
    if (w >= NN) return;
    const float* hr = g_h[0] + (size_t)w * HD;
    float v = hr[lane] * dw[lane] + hr[lane + 32] * dw[lane + 32];
    #pragma unroll
    for (int o = 16; o > 0; o >>= 1) v += __shfl_down_sync(0xffffffffu, v, o);
    if (lane == 0) out[w] = v + db[0];
}

// ---------------- launch ----------------
#define NTILES ((NN + 63) / 64)   // 782

extern "C" void kernel_launch(void* const* d_in, const int* in_sizes, int n_in,
                              void* d_out, int out_size) {
    const float* node_pos  = (const float*)d_in[0];
    const float* node_feat = (const float*)d_in[1];
    const int*   eidx      = (const int*)d_in[2];
    const float* enc_w = (const float*)d_in[3];
    const float* enc_b = (const float*)d_in[4];
    const float* eew   = (const float*)d_in[5];
    const float* eeb   = (const float*)d_in[6];
    const float* ew1   = (const float*)d_in[7];
    const float* eb1   = (const float*)d_in[8];
    const float* ew2   = (const float*)d_in[9];
    const float* eb2   = (const float*)d_in[10];
    const float* nw1   = (const float*)d_in[11];
    const float* nb1   = (const float*)d_in[12];
    const float* nw2   = (const float*)d_in[13];
    const float* nb2   = (const float*)d_in[14];
    const float* dec_w = (const float*)d_in[15];
    const float* dec_b = (const float*)d_in[16];
    float* out = (float*)d_out;

    cudaFuncSetAttribute(uv_kernel, cudaFuncAttributeMaxDynamicSharedMemorySize, UV_SMEM);
    cudaFuncSetAttribute(node_fused<false>, cudaFuncAttributeMaxDynamicSharedMemorySize, NODE_SMEM);
    cudaFuncSetAttribute(node_fused<true>,  cudaFuncAttributeMaxDynamicSharedMemorySize, NODE_SMEM);

    zero_counters<<<(NN + 255) / 256, 256>>>();
    prep_cnt<<<(NE + 255) / 256, 256>>>(eidx);
    scan_counts<<<1, 1024>>>();
    fill_csr<<<(NE + 255) / 256, 256>>>(eidx, node_pos);
    prep_weights<<<(PREPW_TOT + 255) / 256, 256>>>(ew1, eew, eeb, eb1, eb2, nw1, ew2, nw2, nb2);
    encoder<<<(NN * HD + 255) / 256, 256>>>(node_feat, enc_w, enc_b);

    uv_kernel<<<NTILES, 256, UV_SMEM>>>(0);
    for (int l = 0; l < NL; ++l) {
        edge_gather<<<(NN * 32 + 255) / 256, 256>>>(l);
        if (l < NL - 1)
            node_fused<false><<<NTILES, 256, NODE_SMEM>>>(nb1, nb2, l);
        else
            node_fused<true><<<NTILES, 256, NODE_SMEM>>>(nb1, nb2, l);
    }

    decoder<<<(NN * 32 + 255) / 256, 256>>>(dec_w, dec_b, out);
}